// round 3
// baseline (speedup 1.0000x reference)
#include <cuda_runtime.h>
#include <math.h>

// Problem dims
#define BB 64
#define TT 512
#define II 256
#define HH 1024
#define OO 10
#define KTOT (HH + II)      // 1280 combined reduction (h rows then x rows)
#define KT 32               // k-tile depth
#define NKT (KTOT / KT)     // 40 tiles

#define GRID 128            // 2 b-groups x 64 hj-groups (all co-resident)
#define NTHREADS 128        // 8 b-threads x 16 hj-threads

#define ASZ (KT * 36)       // A tile, padded row 36 (16B-aligned float4 rows)
#define BSZ (KT * 64)       // W tile: [kk][hjL(16)][gate(4)]

// Persistent device state
__device__ float g_h[2][BB * HH];
__device__ unsigned int g_count;
__device__ volatile unsigned int g_gen;

__device__ __forceinline__ void grid_sync() {
    __syncthreads();
    if (threadIdx.x == 0) {
        unsigned int my = g_gen;
        __threadfence();
        if (atomicAdd(&g_count, 1u) == GRID - 1) {
            g_count = 0;
            __threadfence();
            g_gen = my + 1;
        } else {
            while (g_gen == my) { }
            __threadfence();
        }
    }
    __syncthreads();
}

// packed fp32x2 FMA: acc = a * w + acc (lanewise on 2 packed fp32)
__device__ __forceinline__ void fma2(unsigned long long& acc,
                                     unsigned long long a,
                                     unsigned long long ww) {
    asm("fma.rn.f32x2 %0, %1, %2, %0;" : "+l"(acc) : "l"(a), "l"(ww));
}
__device__ __forceinline__ unsigned long long pack2(float w) {
    unsigned long long r;
    asm("mov.b64 %0, {%1, %1};" : "=l"(r) : "f"(w));
    return r;
}

__device__ __forceinline__ float4 ldA4(const float* __restrict__ hcur,
                                       const float* __restrict__ x,
                                       int t, int b, int r) {
    return (r < HH) ? *(const float4*)&hcur[b * HH + r]
                    : *(const float4*)&x[b * (TT * II) + t * II + (r - HH)];
}
__device__ __forceinline__ float4 ldW4(const float* __restrict__ Wh,
                                       const float* __restrict__ Wx,
                                       int g, int r, int col) {
    return (r < HH) ? *(const float4*)&Wh[(g * HH + r) * HH + col]
                    : *(const float4*)&Wx[(g * II + (r - HH)) * HH + col];
}

__global__ __launch_bounds__(NTHREADS, 1)
void lstm_persistent_kernel(const float* __restrict__ x,
                            const float* __restrict__ Wx,
                            const float* __restrict__ bx,
                            const float* __restrict__ Wh,
                            const float* __restrict__ bh,
                            const float* __restrict__ Wp,
                            const float* __restrict__ bp,
                            float* __restrict__ out)
{
    __shared__ float As[2][ASZ];
    __shared__ float Bs[2][BSZ];
    __shared__ float red[NTHREADS];
    __shared__ float logits[OO];

    const int tid = threadIdx.x;
    const int bgrp  = blockIdx.x & 1;      // 0..1  -> 32 batch rows
    const int hjgrp = blockIdx.x >> 1;     // 0..63 -> 16 hidden cols
    const int b0  = bgrp * 32;
    const int hj0 = hjgrp * 16;

    // compute-phase mapping
    const int thj = tid & 15;              // hidden col within tile
    const int tb  = tid >> 4;              // 0..7 -> 4 batch rows each
    const int hj  = hj0 + thj;

    // A staging mapping: float4 along k
    const int a_kq = tid & 7;              // k quad: k = a_kq*4 .. +3
    const int a_bl = tid >> 3;             // 0..15; second load adds +16

    // W staging mapping: 4 float4 per thread, float4 along hj
    int w_hjq[4], w_kk[4], w_g[4];
#pragma unroll
    for (int q = 0; q < 4; q++) {
        int idx = tid + q * 128;
        w_hjq[q] = idx & 3;
        w_kk[q]  = (idx >> 2) & 31;
        w_g[q]   = idx >> 7;
    }

    // zero initial hidden state
    for (int idx = blockIdx.x * NTHREADS + tid; idx < BB * HH; idx += GRID * NTHREADS)
        g_h[0][idx] = 0.0f;

    float bias[4];
#pragma unroll
    for (int g = 0; g < 4; g++)
        bias[g] = bh[g * HH + hj] + bx[g * HH + hj];

    float c[4] = {0.f, 0.f, 0.f, 0.f};

    grid_sync();

    for (int t = 0; t < TT; t++) {
        const float* hcur = g_h[t & 1];
        float*       hnxt = g_h[(t + 1) & 1];

        unsigned long long acc[4][2];      // [gate][b-pair]; pair0=(b0,b1) pair1=(b2,b3)
#pragma unroll
        for (int g = 0; g < 4; g++) { acc[g][0] = 0ull; acc[g][1] = 0ull; }

        float4 pa[2], pb[4];

        // prologue: tile 0 -> buf0, then prefetch tile 1 into regs
#pragma unroll
        for (int q = 0; q < 2; q++)
            pa[q] = ldA4(hcur, x, t, b0 + a_bl + q * 16, a_kq * 4);
#pragma unroll
        for (int q = 0; q < 4; q++)
            pb[q] = ldW4(Wh, Wx, w_g[q], w_kk[q], hj0 + w_hjq[q] * 4);
#pragma unroll
        for (int q = 0; q < 2; q++) {
            float* dst = &As[0][(a_kq * 4) * 36 + a_bl + q * 16];
            dst[0]   = pa[q].x; dst[36]  = pa[q].y;
            dst[72]  = pa[q].z; dst[108] = pa[q].w;
        }
#pragma unroll
        for (int q = 0; q < 4; q++) {
            float* dst = &Bs[0][w_kk[q] * 64 + w_hjq[q] * 16 + w_g[q]];
            dst[0] = pb[q].x; dst[4] = pb[q].y; dst[8] = pb[q].z; dst[12] = pb[q].w;
        }
#pragma unroll
        for (int q = 0; q < 2; q++)
            pa[q] = ldA4(hcur, x, t, b0 + a_bl + q * 16, KT + a_kq * 4);
#pragma unroll
        for (int q = 0; q < 4; q++)
            pb[q] = ldW4(Wh, Wx, w_g[q], KT + w_kk[q], hj0 + w_hjq[q] * 4);
        __syncthreads();

        for (int kt = 0; kt < NKT; kt++) {
            const int cur = kt & 1;
            const int nxt = cur ^ 1;

            // stage prefetched tile kt+1 into the other buffer
            if (kt + 1 < NKT) {
#pragma unroll
                for (int q = 0; q < 2; q++) {
                    float* dst = &As[nxt][(a_kq * 4) * 36 + a_bl + q * 16];
                    dst[0]   = pa[q].x; dst[36]  = pa[q].y;
                    dst[72]  = pa[q].z; dst[108] = pa[q].w;
                }
#pragma unroll
                for (int q = 0; q < 4; q++) {
                    float* dst = &Bs[nxt][w_kk[q] * 64 + w_hjq[q] * 16 + w_g[q]];
                    dst[0] = pb[q].x; dst[4] = pb[q].y; dst[8] = pb[q].z; dst[12] = pb[q].w;
                }
            }
            // prefetch tile kt+2 (overlaps with compute below)
            if (kt + 2 < NKT) {
                const int k0 = (kt + 2) * KT;
#pragma unroll
                for (int q = 0; q < 2; q++)
                    pa[q] = ldA4(hcur, x, t, b0 + a_bl + q * 16, k0 + a_kq * 4);
#pragma unroll
                for (int q = 0; q < 4; q++)
                    pb[q] = ldW4(Wh, Wx, w_g[q], k0 + w_kk[q], hj0 + w_hjq[q] * 4);
            }

            // compute on buffer `cur`: 16 MACs in 8 FMA2 per kk
            const float* Ab = &As[cur][tb * 4];
            const float* Bb = &Bs[cur][thj * 4];
#pragma unroll
            for (int kk = 0; kk < KT; kk++) {
                ulonglong2 av = *(const ulonglong2*)(Ab + kk * 36);
                float4     wv = *(const float4*)(Bb + kk * 64);
                unsigned long long ww;
                ww = pack2(wv.x); fma2(acc[0][0], av.x, ww); fma2(acc[0][1], av.y, ww);
                ww = pack2(wv.y); fma2(acc[1][0], av.x, ww); fma2(acc[1][1], av.y, ww);
                ww = pack2(wv.z); fma2(acc[2][0], av.x, ww); fma2(acc[2][1], av.y, ww);
                ww = pack2(wv.w); fma2(acc[3][0], av.x, ww); fma2(acc[3][1], av.y, ww);
            }
            __syncthreads();
        }

        // gate epilogue: unpack packed pairs; thread owns 4 (b,hj) cells
#pragma unroll
        for (int q = 0; q < 4; q++) {
            const int p = q >> 1;
            const int half = q & 1;
            float zg, zi, zf, zo;
            if (half == 0) {
                zg = __uint_as_float((unsigned)(acc[0][p] & 0xffffffffull));
                zi = __uint_as_float((unsigned)(acc[1][p] & 0xffffffffull));
                zf = __uint_as_float((unsigned)(acc[2][p] & 0xffffffffull));
                zo = __uint_as_float((unsigned)(acc[3][p] & 0xffffffffull));
            } else {
                zg = __uint_as_float((unsigned)(acc[0][p] >> 32));
                zi = __uint_as_float((unsigned)(acc[1][p] >> 32));
                zf = __uint_as_float((unsigned)(acc[2][p] >> 32));
                zo = __uint_as_float((unsigned)(acc[3][p] >> 32));
            }
            zg += bias[0]; zi += bias[1]; zf += bias[2]; zo += bias[3];
            float gg = tanhf(zg);
            float ii = 1.0f / (1.0f + __expf(-zi));
            float ff = 1.0f / (1.0f + __expf(-zf));
            float oo = 1.0f / (1.0f + __expf(-zo));
            c[q] = gg * ii + c[q] * ff;
            hnxt[(b0 + tb * 4 + q) * HH + hj] = tanhf(c[q]) * oo;
        }

        grid_sync();
    }

    // final projection + softmax (final h is in buffer 0)
    if (blockIdx.x < BB) {
        const int b = blockIdx.x;
        const float* hfin = g_h[0] + b * HH;
        float part[OO];
#pragma unroll
        for (int o = 0; o < OO; o++) part[o] = 0.f;
        for (int k = tid; k < HH; k += NTHREADS) {
            float hv = hfin[k];
#pragma unroll
            for (int o = 0; o < OO; o++)
                part[o] += hv * Wp[k * OO + o];
        }
        for (int o = 0; o < OO; o++) {
            red[tid] = part[o];
            __syncthreads();
            for (int s = NTHREADS / 2; s > 0; s >>= 1) {
                if (tid < s) red[tid] += red[tid + s];
                __syncthreads();
            }
            if (tid == 0) logits[o] = red[0] + bp[o];
            __syncthreads();
        }
        if (tid == 0) {
            float m = logits[0];
#pragma unroll
            for (int o = 1; o < OO; o++) m = fmaxf(m, logits[o]);
            float s = 0.f, e[OO];
#pragma unroll
            for (int o = 0; o < OO; o++) { e[o] = expf(logits[o] - m); s += e[o]; }
            float inv = 1.0f / s;
#pragma unroll
            for (int o = 0; o < OO; o++) out[b * OO + o] = e[o] * inv;
        }
    }
}

extern "C" void kernel_launch(void* const* d_in, const int* in_sizes, int n_in,
                              void* d_out, int out_size) {
    const float* x  = (const float*)d_in[0];
    const float* Wx = (const float*)d_in[1];
    const float* bx = (const float*)d_in[2];
    const float* Wh = (const float*)d_in[3];
    const float* bh = (const float*)d_in[4];
    const float* Wp = (const float*)d_in[5];
    const float* bp = (const float*)d_in[6];
    float* out = (float*)d_out;

    lstm_persistent_kernel<<<GRID, NTHREADS>>>(x, Wx, bx, Wh, bh, Wp, bp, out);
}

// round 5
// speedup vs baseline: 3.1375x; 3.1375x over previous
#include <cuda_runtime.h>
#include <cuda_bf16.h>
#include <stdint.h>
#include <math.h>

#define BB 64
#define TT 512
#define II 256
#define HH 1024
#define OO 10
#define KTOT 1280
#define NCOL 4096          // 4 gates * 1024 hidden
#define GRID 128
#define NT 128
#define KCH 64
#define NCH 20             // 1280/64

// SMEM layout (per double buffer)
#define ABYTES 4096        // 32 rows * 64 k * 2B
#define BBYTES 8192        // 64 rows * 64 k * 2B
#define BUF_BYTES (2*ABYTES + 2*BBYTES)   // 24576
#define OFF_AHI 0
#define OFF_ALO ABYTES
#define OFF_BHI (2*ABYTES)
#define OFF_BLO (2*ABYTES + BBYTES)
#define DYN_SMEM (2*BUF_BYTES + 1024)     // + reduction scratch

#define SW(o) ((o) ^ (((o) >> 3) & 0x70))

// ---------------- persistent device state ----------------
// weight cols: cf = cta*32 + g*8 + hloc  ->  hj = cta*8 + hloc
__device__ __nv_bfloat16 g_Whi[NCOL * KTOT];
__device__ __nv_bfloat16 g_Wlo[NCOL * KTOT];
__device__ __nv_bfloat16 g_xhi[BB * TT * II];
__device__ __nv_bfloat16 g_xlo[BB * TT * II];
__device__ __nv_bfloat16 g_hhi[2][BB * HH];
__device__ __nv_bfloat16 g_hlo[2][BB * HH];
__device__ unsigned int g_count;
__device__ volatile unsigned int g_gen;

__device__ __forceinline__ uint32_t smem_u32(const void* p) {
    uint32_t a;
    asm("{ .reg .u64 t; cvta.to.shared.u64 t, %1; cvt.u32.u64 %0, t; }" : "=r"(a) : "l"(p));
    return a;
}

#define LDSM4(r, a) \
    asm volatile("ldmatrix.sync.aligned.m8n8.x4.shared.b16 {%0,%1,%2,%3}, [%4];" \
        : "=r"((r)[0]), "=r"((r)[1]), "=r"((r)[2]), "=r"((r)[3]) : "r"(a))

#define MMA(acc, a, b0, b1) \
    asm volatile("mma.sync.aligned.m16n8k16.row.col.f32.bf16.bf16.f32 " \
        "{%0,%1,%2,%3},{%4,%5,%6,%7},{%8,%9},{%0,%1,%2,%3};" \
        : "+f"((acc)[0]), "+f"((acc)[1]), "+f"((acc)[2]), "+f"((acc)[3]) \
        : "r"((a)[0]), "r"((a)[1]), "r"((a)[2]), "r"((a)[3]), "r"(b0), "r"(b1))

__device__ __forceinline__ void grid_sync() {
    __syncthreads();
    if (threadIdx.x == 0) {
        unsigned int my = g_gen;
        __threadfence();
        if (atomicAdd(&g_count, 1u) == GRID - 1) {
            g_count = 0;
            __threadfence();
            g_gen = my + 1;
        } else {
            while (g_gen == my) { }
            __threadfence();
        }
    }
    __syncthreads();
}

// ---------------- setup: split weights/input to bf16 hi/lo ----------------
__global__ void setup_kernel(const float* __restrict__ x,
                             const float* __restrict__ Wx,
                             const float* __restrict__ Wh)
{
    int gt = blockIdx.x * blockDim.x + threadIdx.x;
    int stride = gridDim.x * blockDim.x;

    for (int i = gt; i < NCOL * KTOT; i += stride) {
        int cf = i / KTOT, k = i - cf * KTOT;
        int cta = cf >> 5, r = cf & 31;
        int g = r >> 3, hj = cta * 8 + (r & 7);
        float w = (k < HH) ? Wh[(g * HH + k) * HH + hj]
                           : Wx[(g * II + (k - HH)) * HH + hj];
        __nv_bfloat16 hi = __float2bfloat16(w);
        g_Whi[i] = hi;
        g_Wlo[i] = __float2bfloat16(w - __bfloat162float(hi));
    }
    for (int i = gt; i < BB * TT * II; i += stride) {
        float v = x[i];
        __nv_bfloat16 hi = __float2bfloat16(v);
        g_xhi[i] = hi;
        g_xlo[i] = __float2bfloat16(v - __bfloat162float(hi));
    }
    for (int i = gt; i < BB * HH; i += stride) {
        g_hhi[0][i] = __float2bfloat16(0.0f);
        g_hlo[0][i] = __float2bfloat16(0.0f);
    }
}

// ---------------- persistent HMMA LSTM ----------------
__global__ __launch_bounds__(NT, 1)
void lstm_mma_kernel(const float* __restrict__ bx,
                     const float* __restrict__ bh,
                     const float* __restrict__ Wp,
                     const float* __restrict__ bp,
                     float* __restrict__ out)
{
    extern __shared__ char smem[];
    const uint32_t sb = smem_u32(smem);
    const int tid = threadIdx.x;
    const int w   = tid >> 5;
    const int l   = tid & 31;
    const int cta = blockIdx.x;
    const int col0 = cta * 32;

    // ldmatrix per-lane address components
    const int la = l & 7, lb = (l >> 3) & 1, lc = l >> 4;
    const int offA0 = (0 * 16 + lb * 8 + la) * 128 + lc * 16;   // mt=0
    const int offA1 = (1 * 16 + lb * 8 + la) * 128 + lc * 16;   // mt=1
    const int offB  = (w * 16 + lc * 8 + la) * 128 + lb * 16;

    // staging index components (A: 2 granules/half, B: 4/half)
    const int sa_r  = tid >> 3;            // reused with +16 for q=1
    const int sa_kg = tid & 7;

    // epilogue ownership
    const int hloc = l >> 2;
    const int hj = cta * 8 + hloc;
    float bias[4];
#pragma unroll
    for (int g = 0; g < 4; g++) bias[g] = bh[g * HH + hj] + bx[g * HH + hj];
    float cst[2][2] = {{0.f, 0.f}, {0.f, 0.f}};   // c per [nt][par]
    float cst2[2][2] = {{0.f, 0.f}, {0.f, 0.f}};  // unused split kept simple below
    // c for 4 gates? no: c is per (b,hj): 4 batches per lane -> [nt][par]
    (void)cst2;

    for (int t = 0; t < TT; t++) {
        const __nv_bfloat16* hsH = g_hhi[t & 1];
        const __nv_bfloat16* hsL = g_hlo[t & 1];

        float acc[2][2][4];
#pragma unroll
        for (int mt = 0; mt < 2; mt++)
#pragma unroll
            for (int nt = 0; nt < 2; nt++)
#pragma unroll
                for (int q = 0; q < 4; q++) acc[mt][nt][q] = 0.f;

        uint4 pah[2], pal[2], pbh[4], pbl[4];

        // ---- stage chunk 0 directly ----
        {
            const int kbase = 0;
#pragma unroll
            for (int q = 0; q < 2; q++) {
                int r = sa_r + q * 16;
                int go = (col0 + r) * KTOT + kbase + sa_kg * 8;
                uint4 vh = *(const uint4*)(g_Whi + go);
                uint4 vl = *(const uint4*)(g_Wlo + go);
                int so = SW(r * 128 + sa_kg * 16);
                *(uint4*)(smem + OFF_AHI + so) = vh;
                *(uint4*)(smem + OFF_ALO + so) = vl;
            }
#pragma unroll
            for (int q = 0; q < 4; q++) {
                int n = (tid + q * 128) >> 3;
                int kg = tid & 7;
                int go = n * HH + kbase + kg * 8;
                uint4 vh = __ldcg((const uint4*)(hsH + go));
                uint4 vl = __ldcg((const uint4*)(hsL + go));
                int so = SW(n * 128 + kg * 16);
                *(uint4*)(smem + OFF_BHI + so) = vh;
                *(uint4*)(smem + OFF_BLO + so) = vl;
            }
        }
        // prefetch chunk 1
        {
            const int kbase = KCH;
#pragma unroll
            for (int q = 0; q < 2; q++) {
                int r = sa_r + q * 16;
                int go = (col0 + r) * KTOT + kbase + sa_kg * 8;
                pah[q] = *(const uint4*)(g_Whi + go);
                pal[q] = *(const uint4*)(g_Wlo + go);
            }
#pragma unroll
            for (int q = 0; q < 4; q++) {
                int n = (tid + q * 128) >> 3;
                int kg = tid & 7;
                int go = n * HH + kbase + kg * 8;
                pbh[q] = __ldcg((const uint4*)(hsH + go));
                pbl[q] = __ldcg((const uint4*)(hsL + go));
            }
        }
        __syncthreads();

        for (int j = 0; j < NCH; j++) {
            const int cur = j & 1;
            const char* bufc = smem + cur * BUF_BYTES;

            // stage j+1 into other buffer (regs already loaded)
            if (j + 1 < NCH) {
                char* bufn = smem + (cur ^ 1) * BUF_BYTES;
#pragma unroll
                for (int q = 0; q < 2; q++) {
                    int r = sa_r + q * 16;
                    int so = SW(r * 128 + sa_kg * 16);
                    *(uint4*)(bufn + OFF_AHI + so) = pah[q];
                    *(uint4*)(bufn + OFF_ALO + so) = pal[q];
                }
#pragma unroll
                for (int q = 0; q < 4; q++) {
                    int n = (tid + q * 128) >> 3;
                    int so = SW(n * 128 + (tid & 7) * 16);
                    *(uint4*)(bufn + OFF_BHI + so) = pbh[q];
                    *(uint4*)(bufn + OFF_BLO + so) = pbl[q];
                }
            }
            // prefetch chunk j+2
            if (j + 2 < NCH) {
                const int kbase = (j + 2) * KCH;
#pragma unroll
                for (int q = 0; q < 2; q++) {
                    int r = sa_r + q * 16;
                    int go = (col0 + r) * KTOT + kbase + sa_kg * 8;
                    pah[q] = *(const uint4*)(g_Whi + go);
                    pal[q] = *(const uint4*)(g_Wlo + go);
                }
#pragma unroll
                for (int q = 0; q < 4; q++) {
                    int n = (tid + q * 128) >> 3;
                    int kg = tid & 7;
                    if (kbase < HH) {
                        int go = n * HH + kbase + kg * 8;
                        pbh[q] = __ldcg((const uint4*)(hsH + go));
                        pbl[q] = __ldcg((const uint4*)(hsL + go));
                    } else {
                        int go = (n * TT + t) * II + (kbase - HH) + kg * 8;
                        pbh[q] = __ldcg((const uint4*)(g_xhi + go));
                        pbl[q] = __ldcg((const uint4*)(g_xlo + go));
                    }
                }
            }

            // compute current chunk: 4 k16 steps
            const uint32_t aHiB = sb + cur * BUF_BYTES + OFF_AHI;
            const uint32_t aLoB = sb + cur * BUF_BYTES + OFF_ALO;
            const uint32_t bHiB = sb + cur * BUF_BYTES + OFF_BHI;
            const uint32_t bLoB = sb + cur * BUF_BYTES + OFF_BLO;
#pragma unroll
            for (int ks = 0; ks < 4; ks++) {
                uint32_t ah0[4], ah1[4], al0[4], al1[4], bhf[4], blf[4];
                LDSM4(ah0, aHiB + SW(offA0 + ks * 32));
                LDSM4(ah1, aHiB + SW(offA1 + ks * 32));
                LDSM4(al0, aLoB + SW(offA0 + ks * 32));
                LDSM4(al1, aLoB + SW(offA1 + ks * 32));
                LDSM4(bhf, bHiB + SW(offB + ks * 32));
                LDSM4(blf, bLoB + SW(offB + ks * 32));
                // pass 1: hi*hi
                MMA(acc[0][0], ah0, bhf[0], bhf[1]);
                MMA(acc[0][1], ah0, bhf[2], bhf[3]);
                MMA(acc[1][0], ah1, bhf[0], bhf[1]);
                MMA(acc[1][1], ah1, bhf[2], bhf[3]);
                // pass 2: hi*lo
                MMA(acc[0][0], ah0, blf[0], blf[1]);
                MMA(acc[0][1], ah0, blf[2], blf[3]);
                MMA(acc[1][0], ah1, blf[0], blf[1]);
                MMA(acc[1][1], ah1, blf[2], blf[3]);
                // pass 3: lo*hi
                MMA(acc[0][0], al0, bhf[0], bhf[1]);
                MMA(acc[0][1], al0, bhf[2], bhf[3]);
                MMA(acc[1][0], al1, bhf[0], bhf[1]);
                MMA(acc[1][1], al1, bhf[2], bhf[3]);
            }
            __syncthreads();
        }

        // ---- epilogue: fully register-resident LSTM cell update ----
        __nv_bfloat16* hdH = g_hhi[(t + 1) & 1];
        __nv_bfloat16* hdL = g_hlo[(t + 1) & 1];
#pragma unroll
        for (int nt = 0; nt < 2; nt++) {
#pragma unroll
            for (int par = 0; par < 2; par++) {
                float zg = acc[0][nt][par]     + bias[0];
                float zi = acc[0][nt][2 + par] + bias[1];
                float zf = acc[1][nt][par]     + bias[2];
                float zo = acc[1][nt][2 + par] + bias[3];
                float gg = tanhf(zg);
                float ii = 1.0f / (1.0f + __expf(-zi));
                float ff = 1.0f / (1.0f + __expf(-zf));
                float oo = 1.0f / (1.0f + __expf(-zo));
                float cc = gg * ii + cst[nt][par] * ff;
                cst[nt][par] = cc;
                float hv = tanhf(cc) * oo;
                int b = w * 16 + nt * 8 + 2 * (l & 3) + par;
                __nv_bfloat16 hi = __float2bfloat16(hv);
                hdH[b * HH + hj] = hi;
                hdL[b * HH + hj] = __float2bfloat16(hv - __bfloat162float(hi));
            }
        }
        grid_sync();
    }

    // ---------- final projection + softmax (final h in parity 0: TT even) ----------
    if (blockIdx.x < BB) {
        float* red    = (float*)(smem + 2 * BUF_BYTES);
        float* logits = red + NT;
        const int b = blockIdx.x;
        float part[OO];
#pragma unroll
        for (int o = 0; o < OO; o++) part[o] = 0.f;
        for (int k = tid; k < HH; k += NT) {
            float hv = __bfloat162float(g_hhi[0][b * HH + k])
                     + __bfloat162float(g_hlo[0][b * HH + k]);
#pragma unroll
            for (int o = 0; o < OO; o++) part[o] += hv * Wp[k * OO + o];
        }
        for (int o = 0; o < OO; o++) {
            red[tid] = part[o];
            __syncthreads();
            for (int s = NT / 2; s > 0; s >>= 1) {
                if (tid < s) red[tid] += red[tid + s];
                __syncthreads();
            }
            if (tid == 0) logits[o] = red[0] + bp[o];
            __syncthreads();
        }
        if (tid == 0) {
            float m = logits[0];
#pragma unroll
            for (int o = 1; o < OO; o++) m = fmaxf(m, logits[o]);
            float s = 0.f, e[OO];
#pragma unroll
            for (int o = 0; o < OO; o++) { e[o] = expf(logits[o] - m); s += e[o]; }
            float inv = 1.0f / s;
#pragma unroll
            for (int o = 0; o < OO; o++) out[b * OO + o] = e[o] * inv;
        }
    }
}

extern "C" void kernel_launch(void* const* d_in, const int* in_sizes, int n_in,
                              void* d_out, int out_size) {
    const float* x  = (const float*)d_in[0];
    const float* Wx = (const float*)d_in[1];
    const float* bx = (const float*)d_in[2];
    const float* Wh = (const float*)d_in[3];
    const float* bh = (const float*)d_in[4];
    const float* Wp = (const float*)d_in[5];
    const float* bp = (const float*)d_in[6];
    float* out = (float*)d_out;

    cudaFuncSetAttribute(lstm_mma_kernel, cudaFuncAttributeMaxDynamicSharedMemorySize, DYN_SMEM);
    setup_kernel<<<512, 256>>>(x, Wx, Wh);
    lstm_mma_kernel<<<GRID, NT, DYN_SMEM>>>(bx, bh, Wp, bp, out);
}

// round 6
// speedup vs baseline: 4.0795x; 1.3003x over previous
#include <cuda_runtime.h>
#include <cuda_bf16.h>
#include <stdint.h>
#include <math.h>

#define BB 64
#define TT 512
#define II 256
#define HH 1024
#define OO 10
#define KTOT 1280
#define NCOL 4096
#define GRID 128
#define NT 128

#define AROW 2560            // bytes per resident-A row (1280 k * 2B)
#define OFF_ALO 81920        // A-lo plane offset
#define OFF_B   163840       // B superbuffers
#define SBUF    32768        // 2 chunk-slots * (hi 8KB + lo 8KB)
#define DYN_SMEM 229376      // 160KB A + 64KB B

#define SW(o) ((o) ^ (((o) >> 3) & 0x70))

// ---------------- persistent device state ----------------
__device__ __nv_bfloat16 g_Whi[NCOL * KTOT];   // [col][k], col = cta*32 + g*8 + hloc
__device__ __nv_bfloat16 g_Wlo[NCOL * KTOT];
__device__ __nv_bfloat16 g_xhi[BB * TT * II];
__device__ __nv_bfloat16 g_xlo[BB * TT * II];
__device__ __nv_bfloat16 g_hhi[2][BB * HH];
__device__ __nv_bfloat16 g_hlo[2][BB * HH];
__device__ unsigned int g_count;
__device__ volatile unsigned int g_gen;

__device__ __forceinline__ uint32_t smem_u32(const void* p) {
    uint32_t a;
    asm("{ .reg .u64 t; cvta.to.shared.u64 t, %1; cvt.u32.u64 %0, t; }" : "=r"(a) : "l"(p));
    return a;
}

#define LDSM4(r, a) \
    asm volatile("ldmatrix.sync.aligned.m8n8.x4.shared.b16 {%0,%1,%2,%3}, [%4];" \
        : "=r"((r)[0]), "=r"((r)[1]), "=r"((r)[2]), "=r"((r)[3]) : "r"(a))

#define MMA(acc, a, b0, b1) \
    asm volatile("mma.sync.aligned.m16n8k16.row.col.f32.bf16.bf16.f32 " \
        "{%0,%1,%2,%3},{%4,%5,%6,%7},{%8,%9},{%0,%1,%2,%3};" \
        : "+f"((acc)[0]), "+f"((acc)[1]), "+f"((acc)[2]), "+f"((acc)[3]) \
        : "r"((a)[0]), "r"((a)[1]), "r"((a)[2]), "r"((a)[3]), "r"(b0), "r"(b1))

#define CP_ASYNC(dst, src) \
    asm volatile("cp.async.cg.shared.global [%0], [%1], 16;" :: "r"(dst), "l"(src))
#define CP_COMMIT() asm volatile("cp.async.commit_group;" ::: "memory")
#define CP_WAIT0()  asm volatile("cp.async.wait_group 0;" ::: "memory")
#define CP_WAIT1()  asm volatile("cp.async.wait_group 1;" ::: "memory")

__device__ __forceinline__ void grid_sync() {
    __syncthreads();
    if (threadIdx.x == 0) {
        unsigned int my = g_gen;
        __threadfence();
        if (atomicAdd(&g_count, 1u) == GRID - 1) {
            g_count = 0;
            __threadfence();
            g_gen = my + 1;
        } else {
            while (g_gen == my) { }
            __threadfence();
        }
    }
    __syncthreads();
}

// ---------------- setup: split weights/input to bf16 hi/lo ----------------
__global__ void setup_kernel(const float* __restrict__ x,
                             const float* __restrict__ Wx,
                             const float* __restrict__ Wh)
{
    int gt = blockIdx.x * blockDim.x + threadIdx.x;
    int stride = gridDim.x * blockDim.x;

    for (int i = gt; i < NCOL * KTOT; i += stride) {
        int cf = i / KTOT, k = i - cf * KTOT;
        int cta = cf >> 5, r = cf & 31;
        int g = r >> 3, hj = cta * 8 + (r & 7);
        float w = (k < HH) ? Wh[(g * HH + k) * HH + hj]
                           : Wx[(g * II + (k - HH)) * HH + hj];
        __nv_bfloat16 hi = __float2bfloat16(w);
        g_Whi[i] = hi;
        g_Wlo[i] = __float2bfloat16(w - __bfloat162float(hi));
    }
    for (int i = gt; i < BB * TT * II; i += stride) {
        float v = x[i];
        __nv_bfloat16 hi = __float2bfloat16(v);
        g_xhi[i] = hi;
        g_xlo[i] = __float2bfloat16(v - __bfloat162float(hi));
    }
    for (int i = gt; i < BB * HH; i += stride) {
        g_hhi[0][i] = __float2bfloat16(0.0f);
        g_hlo[0][i] = __float2bfloat16(0.0f);
    }
}

// ---------------- persistent HMMA LSTM, SMEM-resident weights ----------------
__global__ __launch_bounds__(NT, 1)
void lstm_mma_kernel(const float* __restrict__ bx,
                     const float* __restrict__ bh,
                     const float* __restrict__ Wp,
                     const float* __restrict__ bp,
                     float* __restrict__ out)
{
    extern __shared__ char smem[];
    const uint32_t sb = smem_u32(smem);
    const int tid = threadIdx.x;
    const int w   = tid >> 5;
    const int l   = tid & 31;
    const int cta = blockIdx.x;
    const int col0 = cta * 32;
    const int nh = w & 1;          // n-half: batches nh*32..+31
    const int kh = w >> 1;         // k-split: even/odd chunks

    const int la = l & 7, lb = (l >> 3) & 1, lc = l >> 4;

    // A lane base addresses (resident region, hi plane)
    const uint32_t aB0 = sb + (uint32_t)((lb * 8 + la) * AROW);
    const uint32_t aB1 = aB0 + 16 * AROW;
    // B lane row offsets within a chunk-slot
    const uint32_t bR0 = (uint32_t)((nh * 32 + lc * 8 + la) * 128);
    const uint32_t bR1 = bR0 + 16 * 128;

    // ---- one-time: load resident A (hi+lo) via cp.async ----
#pragma unroll 4
    for (int s = 0; s < 80; s++) {
        int idx = tid + s * 128;
        int hilo = idx >= 5120;
        int rem = hilo ? idx - 5120 : idx;
        int r = rem / 160, kg = rem - r * 160;
        const __nv_bfloat16* src = (hilo ? g_Wlo : g_Whi) + (col0 + r) * KTOT + kg * 8;
        uint32_t dst = sb + (hilo ? OFF_ALO : 0) + r * AROW + (((kg ^ (r & 7))) * 16);
        CP_ASYNC(dst, src);
    }
    CP_COMMIT(); CP_WAIT0();
    __syncthreads();

    // epilogue ownership (warps 0,1 only do the cell update)
    const int hj = cta * 8 + (l >> 2);
    float bias[4];
#pragma unroll
    for (int g = 0; g < 4; g++) bias[g] = bh[g * HH + hj] + bx[g * HH + hj];
    float cc[8];
#pragma unroll
    for (int q = 0; q < 8; q++) cc[q] = 0.f;

    for (int t = 0; t < TT; t++) {
        const __nv_bfloat16* hsH = g_hhi[t & 1];
        const __nv_bfloat16* hsL = g_hlo[t & 1];

        // ---- stage prologue: superbuf0 <- chunks 0,1 ; superbuf1 <- chunks 2,3 ----
#pragma unroll
        for (int ib = 0; ib < 2; ib++) {
            uint32_t base = sb + OFF_B + ib * SBUF;
            int c0 = ib * 2;
#pragma unroll
            for (int s = 0; s < 16; s++) {
                int gi = tid + s * 128;
                int slot = gi >> 10;
                int rem = gi & 1023;
                int hilo = rem >> 9;
                int rem2 = rem & 511;
                int n = rem2 >> 3, kg = rem2 & 7;
                int k = (c0 + slot) * 64 + kg * 8;
                const __nv_bfloat16* src = (hilo ? hsL : hsH) + n * HH + k;
                uint32_t dst = base + slot * 16384 + hilo * 8192 + SW(n * 128 + kg * 16);
                CP_ASYNC(dst, src);
            }
            CP_COMMIT();
        }

        float acc[2][4][4];
#pragma unroll
        for (int mt = 0; mt < 2; mt++)
#pragma unroll
            for (int nf = 0; nf < 4; nf++)
#pragma unroll
                for (int e = 0; e < 4; e++) acc[mt][nf][e] = 0.f;

        for (int i = 0; i < 10; i++) {
            if (i == 9) { CP_WAIT0(); } else { CP_WAIT1(); }
            __syncthreads();

            const int chunk = 2 * i + kh;
            const uint32_t bufB = sb + OFF_B + (i & 1) * SBUF + kh * 16384;
#pragma unroll
            for (int ks = 0; ks < 4; ks++) {
                uint32_t ah0[4], ah1[4], al0[4], al1[4], bhf[8], blf[8];
                uint32_t aoff = (uint32_t)(((chunk * 8 + ks * 2 + lc) ^ la) * 16);
                LDSM4(ah0, aB0 + aoff);
                LDSM4(ah1, aB1 + aoff);
                LDSM4(al0, aB0 + OFF_ALO + aoff);
                LDSM4(al1, aB1 + OFF_ALO + aoff);
                uint32_t boff = (uint32_t)((((ks * 2 + lb) ^ la)) * 16);
                LDSM4(bhf,     bufB + bR0 + boff);
                LDSM4(bhf + 4, bufB + bR1 + boff);
                LDSM4(blf,     bufB + 8192 + bR0 + boff);
                LDSM4(blf + 4, bufB + 8192 + bR1 + boff);
                // pass 1: hi*hi  (8 independent accs)
                MMA(acc[0][0], ah0, bhf[0], bhf[1]);
                MMA(acc[0][1], ah0, bhf[2], bhf[3]);
                MMA(acc[0][2], ah0, bhf[4], bhf[5]);
                MMA(acc[0][3], ah0, bhf[6], bhf[7]);
                MMA(acc[1][0], ah1, bhf[0], bhf[1]);
                MMA(acc[1][1], ah1, bhf[2], bhf[3]);
                MMA(acc[1][2], ah1, bhf[4], bhf[5]);
                MMA(acc[1][3], ah1, bhf[6], bhf[7]);
                // pass 2: hi*lo
                MMA(acc[0][0], ah0, blf[0], blf[1]);
                MMA(acc[0][1], ah0, blf[2], blf[3]);
                MMA(acc[0][2], ah0, blf[4], blf[5]);
                MMA(acc[0][3], ah0, blf[6], blf[7]);
                MMA(acc[1][0], ah1, blf[0], blf[1]);
                MMA(acc[1][1], ah1, blf[2], blf[3]);
                MMA(acc[1][2], ah1, blf[4], blf[5]);
                MMA(acc[1][3], ah1, blf[6], blf[7]);
                // pass 3: lo*hi
                MMA(acc[0][0], al0, bhf[0], bhf[1]);
                MMA(acc[0][1], al0, bhf[2], bhf[3]);
                MMA(acc[0][2], al0, bhf[4], bhf[5]);
                MMA(acc[0][3], al0, bhf[6], bhf[7]);
                MMA(acc[1][0], al1, bhf[0], bhf[1]);
                MMA(acc[1][1], al1, bhf[2], bhf[3]);
                MMA(acc[1][2], al1, bhf[4], bhf[5]);
                MMA(acc[1][3], al1, bhf[6], bhf[7]);
            }
            __syncthreads();   // everyone done with superbuf (i&1) before restage

            if (i < 8) {
                uint32_t base = sb + OFF_B + (i & 1) * SBUF;
                int c0 = 2 * i + 4;
#pragma unroll
                for (int s = 0; s < 16; s++) {
                    int gi = tid + s * 128;
                    int slot = gi >> 10;
                    int rem = gi & 1023;
                    int hilo = rem >> 9;
                    int rem2 = rem & 511;
                    int n = rem2 >> 3, kg = rem2 & 7;
                    int k = (c0 + slot) * 64 + kg * 8;
                    const __nv_bfloat16* src;
                    if (k < HH) src = (hilo ? hsL : hsH) + n * HH + k;
                    else        src = (hilo ? g_xlo : g_xhi) + (n * TT + t) * II + (k - HH);
                    uint32_t dst = base + slot * 16384 + hilo * 8192 + SW(n * 128 + kg * 16);
                    CP_ASYNC(dst, src);
                }
                CP_COMMIT();
            }
        }

        // ---- k-split reduction: warps {2,3} -> scratch -> warps {0,1} ----
        float* scratch = (float*)(smem + OFF_B);   // 8KB, superbuf0 region (consumed)
        if (kh == 1) {
#pragma unroll
            for (int mt = 0; mt < 2; mt++)
#pragma unroll
                for (int nf = 0; nf < 4; nf++)
#pragma unroll
                    for (int e = 0; e < 4; e++)
                        scratch[nh * 1024 + (mt * 16 + nf * 4 + e) * 32 + l] = acc[mt][nf][e];
        }
        __syncthreads();

        if (kh == 0) {
#pragma unroll
            for (int mt = 0; mt < 2; mt++)
#pragma unroll
                for (int nf = 0; nf < 4; nf++)
#pragma unroll
                    for (int e = 0; e < 4; e++)
                        acc[mt][nf][e] += scratch[nh * 1024 + (mt * 16 + nf * 4 + e) * 32 + l];

            __nv_bfloat16* hdH = g_hhi[(t + 1) & 1];
            __nv_bfloat16* hdL = g_hlo[(t + 1) & 1];
#pragma unroll
            for (int nf = 0; nf < 4; nf++) {
#pragma unroll
                for (int par = 0; par < 2; par++) {
                    float zg = acc[0][nf][par]     + bias[0];
                    float zi = acc[0][nf][2 + par] + bias[1];
                    float zf = acc[1][nf][par]     + bias[2];
                    float zo = acc[1][nf][2 + par] + bias[3];
                    float gg = tanhf(zg);
                    float ii = 1.0f / (1.0f + __expf(-zi));
                    float ff = 1.0f / (1.0f + __expf(-zf));
                    float oo = 1.0f / (1.0f + __expf(-zo));
                    float cv = gg * ii + cc[nf * 2 + par] * ff;
                    cc[nf * 2 + par] = cv;
                    float hv = tanhf(cv) * oo;
                    int b = nh * 32 + nf * 8 + 2 * (l & 3) + par;
                    __nv_bfloat16 hi = __float2bfloat16(hv);
                    hdH[b * HH + hj] = hi;
                    hdL[b * HH + hj] = __float2bfloat16(hv - __bfloat162float(hi));
                }
            }
        }
        grid_sync();
    }

    // ---------- final projection + softmax (final h in buffer 0) ----------
    if (blockIdx.x < BB) {
        float* red    = (float*)(smem + OFF_B);
        float* logits = red + NT;
        const int b = blockIdx.x;
        float part[OO];
#pragma unroll
        for (int o = 0; o < OO; o++) part[o] = 0.f;
        for (int k = tid; k < HH; k += NT) {
            float hv = __bfloat162float(g_hhi[0][b * HH + k])
                     + __bfloat162float(g_hlo[0][b * HH + k]);
#pragma unroll
            for (int o = 0; o < OO; o++) part[o] += hv * Wp[k * OO + o];
        }
        for (int o = 0; o < OO; o++) {
            red[tid] = part[o];
            __syncthreads();
            for (int s = NT / 2; s > 0; s >>= 1) {
                if (tid < s) red[tid] += red[tid + s];
                __syncthreads();
            }
            if (tid == 0) logits[o] = red[0] + bp[o];
            __syncthreads();
        }
        if (tid == 0) {
            float m = logits[0];
#pragma unroll
            for (int o = 1; o < OO; o++) m = fmaxf(m, logits[o]);
            float s = 0.f, e[OO];
#pragma unroll
            for (int o = 0; o < OO; o++) { e[o] = expf(logits[o] - m); s += e[o]; }
            float inv = 1.0f / s;
#pragma unroll
            for (int o = 0; o < OO; o++) out[b * OO + o] = e[o] * inv;
        }
    }
}

extern "C" void kernel_launch(void* const* d_in, const int* in_sizes, int n_in,
                              void* d_out, int out_size) {
    const float* x  = (const float*)d_in[0];
    const float* Wx = (const float*)d_in[1];
    const float* bx = (const float*)d_in[2];
    const float* Wh = (const float*)d_in[3];
    const float* bh = (const float*)d_in[4];
    const float* Wp = (const float*)d_in[5];
    const float* bp = (const float*)d_in[6];
    float* out = (float*)d_out;

    cudaFuncSetAttribute(lstm_mma_kernel, cudaFuncAttributeMaxDynamicSharedMemorySize, DYN_SMEM);
    setup_kernel<<<512, 256>>>(x, Wx, Wh);
    lstm_mma_kernel<<<GRID, NT, DYN_SMEM>>>(bx, bh, Wp, bp, out);
}